// round 11
// baseline (speedup 1.0000x reference)
#include <cuda_runtime.h>
#include <cuda_fp16.h>
#include <math.h>
#include <stdint.h>

#define N_NODES 2048
#define BATCH   32
#define HIDDEN  64
#define C_IN    66                 // DIM_IN + HIDDEN
#define BC      2112               // BATCH * C_IN
#define NPAD    2176               // BC padded to multiple of 128
#define IN3     198                // 3 * C_IN
#define GATE_OUT 128
#define UPD_OUT  64

// ---------------- device scratch (static: no allocations allowed) ----------
__device__ __half g_Ah  [N_NODES * N_NODES];
__device__ __half g_T0hi[NPAD * N_NODES];   // X0T / C0T
__device__ __half g_T0lo[NPAD * N_NODES];
__device__ __half g_T1hi[NPAD * N_NODES];   // X1T / C1T
__device__ __half g_T1lo[NPAD * N_NODES];
__device__ __half g_T2hi[NPAD * N_NODES];   // Y2T / Y4T (raw A@X1 / A@C1)
__device__ __half g_T2lo[NPAD * N_NODES];
__device__ float g_P [N_NODES * BC];        // X0 fp32, then C0 fp32
__device__ float g_r [BATCH * N_NODES * HIDDEN];
__device__ float g_Wg2[IN3 * GATE_OUT];     // folded gate weights
__device__ float g_Wu2[IN3 * UPD_OUT];      // folded update weights

__device__ __forceinline__ uint32_t smem_to_u32(const void* p) {
    uint32_t a;
    asm("{ .reg .u64 t; cvta.to.shared.u64 t, %1; cvt.u32.u64 %0, t; }" : "=r"(a) : "l"(p));
    return a;
}
__device__ __forceinline__ void split_fp16(float v, __half& hi, __half& lo) {
    hi = __float2half_rn(v);
    lo = __float2half_rn(v - __half2float(hi));
}
__device__ __forceinline__ void mma_fp16(float* c, const uint32_t* a, const uint32_t* b) {
    asm volatile(
        "mma.sync.aligned.m16n8k16.row.col.f32.f16.f16.f32 "
        "{%0,%1,%2,%3}, {%4,%5,%6,%7}, {%8,%9}, {%0,%1,%2,%3};"
        : "+f"(c[0]), "+f"(c[1]), "+f"(c[2]), "+f"(c[3])
        : "r"(a[0]), "r"(a[1]), "r"(a[2]), "r"(a[3]), "r"(b[0]), "r"(b[1]));
}
__device__ __forceinline__ void ldsm4(uint32_t* r, uint32_t addr) {
    asm volatile("ldmatrix.sync.aligned.m8n8.x4.shared.b16 {%0,%1,%2,%3}, [%4];"
                 : "=r"(r[0]), "=r"(r[1]), "=r"(r[2]), "=r"(r[3]) : "r"(addr));
}
__device__ __forceinline__ void cp16(uint32_t daddr, const void* g) {
    asm volatile("cp.async.cg.shared.global [%0], [%1], 16;" :: "r"(daddr), "l"(g));
}
__device__ __forceinline__ unsigned long long pack_dup(float b) {
    unsigned long long r;
    asm("mov.b64 %0, {%1, %1};" : "=l"(r) : "f"(b));
    return r;
}
__device__ __forceinline__ void ffma2(unsigned long long& d,
                                      unsigned long long a,
                                      unsigned long long b) {
    asm("fma.rn.f32x2 %0, %1, %2, %0;" : "+l"(d) : "l"(a), "l"(b));
}

// ---------------- K1: supports = softmax(relu(E E^T)) -> fp16 --------------
__global__ void supports_kernel(const float* __restrict__ E) {
    int n = blockIdx.x;
    int t = threadIdx.x;
    float e[10];
#pragma unroll
    for (int c = 0; c < 10; c++) e[c] = E[n * 10 + c];

    float vals[8];
    float vmax = 0.0f;
#pragma unroll
    for (int j = 0; j < 8; j++) {
        int m = j * 256 + t;
        float s = 0.0f;
#pragma unroll
        for (int c = 0; c < 10; c++) s = fmaf(e[c], E[m * 10 + c], s);
        s = fmaxf(s, 0.0f);
        vals[j] = s;
        vmax = fmaxf(vmax, s);
    }
    __shared__ float red[256];
    red[t] = vmax; __syncthreads();
    for (int s = 128; s > 0; s >>= 1) {
        if (t < s) red[t] = fmaxf(red[t], red[t + s]);
        __syncthreads();
    }
    vmax = red[0]; __syncthreads();

    float lsum = 0.0f;
#pragma unroll
    for (int j = 0; j < 8; j++) { vals[j] = expf(vals[j] - vmax); lsum += vals[j]; }
    red[t] = lsum; __syncthreads();
    for (int s = 128; s > 0; s >>= 1) {
        if (t < s) red[t] += red[t + s];
        __syncthreads();
    }
    float inv = 1.0f / red[0];
#pragma unroll
    for (int j = 0; j < 8; j++)
        g_Ah[(size_t)n * N_NODES + j * 256 + t] = __float2half_rn(vals[j] * inv);
}

// ---------------- K2: pack X0 fp32 [node][bc] (coalesced) ------------------
__global__ void pack_kernel(const float* __restrict__ x, const float* __restrict__ st) {
    int n = blockIdx.x;
    for (int i = threadIdx.x; i < BC; i += blockDim.x) {
        int b = i / C_IN, c = i - b * C_IN;
        float v = (c < 2) ? x[(b * N_NODES + n) * 2 + c]
                          : st[(b * N_NODES + n) * 64 + (c - 2)];
        g_P[n * BC + i] = v;
    }
}

// ---------------- K2b: fold Chebyshev into weights -------------------------
// W'0 = W0 - W2 ; W'1 = W1 ; W'2 = 2*W2   (so [X0,X1,2AX1-X0]W == [X0,X1,AX1]W')
__global__ void wfold_kernel(const float* __restrict__ Wg, const float* __restrict__ Wu) {
    int idx = blockIdx.x * 256 + threadIdx.x;
    if (idx < C_IN * GATE_OUT) {                       // 8448: per (c,o) gate
        int c = idx / GATE_OUT, o = idx - c * GATE_OUT;
        float w0 = Wg[(c)            * GATE_OUT + o];
        float w1 = Wg[(C_IN + c)     * GATE_OUT + o];
        float w2 = Wg[(2 * C_IN + c) * GATE_OUT + o];
        g_Wg2[(c)            * GATE_OUT + o] = w0 - w2;
        g_Wg2[(C_IN + c)     * GATE_OUT + o] = w1;
        g_Wg2[(2 * C_IN + c) * GATE_OUT + o] = 2.f * w2;
    }
    if (idx < C_IN * UPD_OUT) {                        // 4224: per (c,o) update
        int c = idx / UPD_OUT, o = idx - c * UPD_OUT;
        float w0 = Wu[(c)            * UPD_OUT + o];
        float w1 = Wu[(C_IN + c)     * UPD_OUT + o];
        float w2 = Wu[(2 * C_IN + c) * UPD_OUT + o];
        g_Wu2[(c)            * UPD_OUT + o] = w0 - w2;
        g_Wu2[(C_IN + c)     * UPD_OUT + o] = w1;
        g_Wu2[(2 * C_IN + c) * UPD_OUT + o] = 2.f * w2;
    }
}

// ---------------- K3: tiled transpose+split: src[N][BC] -> dst[NPAD][N] ----
__global__ void __launch_bounds__(256)
transpose_split_kernel(const float* __restrict__ src,
                       __half* __restrict__ dhi,
                       __half* __restrict__ dlo) {
    __shared__ float tile[64][65];
    int i0 = blockIdx.x * 64;
    int n0 = blockIdx.y * 64;
    int t = threadIdx.x;
    int iloc = t >> 2;
    int seg  = (t & 3) * 16;

    if (i0 < BC) {
        int nloc = t >> 2;
#pragma unroll
        for (int g = 0; g < 4; g++) {
            float4 v = *(const float4*)(src + (size_t)(n0 + nloc) * BC + i0 + seg + g * 4);
            tile[seg + g * 4 + 0][nloc] = v.x;
            tile[seg + g * 4 + 1][nloc] = v.y;
            tile[seg + g * 4 + 2][nloc] = v.z;
            tile[seg + g * 4 + 3][nloc] = v.w;
        }
        __syncthreads();
        __half hi[16], lo[16];
#pragma unroll
        for (int g = 0; g < 16; g++)
            split_fp16(tile[iloc][seg + g], hi[g], lo[g]);
        size_t off = (size_t)(i0 + iloc) * N_NODES + n0 + seg;
        *(uint4*)(dhi + off)     = *(uint4*)&hi[0];
        *(uint4*)(dhi + off + 8) = *(uint4*)&hi[8];
        *(uint4*)(dlo + off)     = *(uint4*)&lo[0];
        *(uint4*)(dlo + off + 8) = *(uint4*)&lo[8];
    } else {
        uint4 z = make_uint4(0, 0, 0, 0);
        size_t off = (size_t)(i0 + iloc) * N_NODES + n0 + seg;
        *(uint4*)(dhi + off)     = z;
        *(uint4*)(dhi + off + 8) = z;
        *(uint4*)(dlo + off)     = z;
        *(uint4*)(dlo + off + 8) = z;
    }
}

// ---------------- HMMA GEMM: raw D = A @ B^T, output fp16-split T only -----
// fp16 2-split (A*Bhi + A*Blo), fp32 acc. CTA 256x128, 8 warps 64x64, BK=32.
__global__ void __launch_bounds__(256, 1)
mma_gemm(const __half* __restrict__ Ah,
         const __half* __restrict__ Bhi, const __half* __restrict__ Blo,
         __half* __restrict__ CThi, __half* __restrict__ CTlo) {
    extern __shared__ char smem[];
    const uint32_t sb = smem_to_u32(smem);
    const int tid = threadIdx.x, wid = tid >> 5, lane = tid & 31;
    const int wr = wid >> 1, wc = wid & 1;            // warp tile: 64x64
    const int m0 = blockIdx.y * 256, n0 = blockIdx.x * 128;

    const __half* srcA = Ah + (size_t)m0 * N_NODES;
    const __half* srcB[2] = { Bhi + (size_t)n0 * N_NODES,
                              Blo + (size_t)n0 * N_NODES };

    float acc[4][8][4];
#pragma unroll
    for (int i = 0; i < 4; i++)
#pragma unroll
        for (int j = 0; j < 8; j++)
#pragma unroll
            for (int k = 0; k < 4; k++) acc[i][j][k] = 0.f;

#define COPY_CHUNK(k0, bufi) do {                                             \
        uint32_t _b = sb + (bufi) * 49152;                                    \
        _Pragma("unroll")                                                     \
        for (int _u = 0; _u < 4; _u++) {                                      \
            int _unit = _u * 256 + tid;                                       \
            int _row = _unit >> 2, _q = _unit & 3;                            \
            int _sl = _q >> 1, _hf = _q & 1;                                  \
            cp16(_b + _sl * 12288 + _row * 48 + _hf * 16,                     \
                 srcA + (size_t)_row * N_NODES + (k0) + _sl * 16 + _hf * 8);  \
        }                                                                     \
        _Pragma("unroll")                                                     \
        for (int _t = 0; _t < 2; _t++) {                                      \
            _Pragma("unroll")                                                 \
            for (int _u = 0; _u < 2; _u++) {                                  \
                int _unit = _u * 256 + tid;                                   \
                int _row = _unit >> 2, _q = _unit & 3;                        \
                int _sl = _q >> 1, _hf = _q & 1;                              \
                cp16(_b + 24576 + _t * 12288 + _sl * 6144 + _row * 48 + _hf * 16, \
                     srcB[_t] + (size_t)_row * N_NODES + (k0) + _sl * 16 + _hf * 8); \
            }                                                                 \
        }                                                                     \
        asm volatile("cp.async.commit_group;");                               \
    } while (0)

    COPY_CHUNK(0, 0);

    const int NCHUNK = N_NODES / 32;   // 64
    for (int c = 0; c < NCHUNK; c++) {
        int buf = c & 1;
        if (c + 1 < NCHUNK) {
            COPY_CHUNK((c + 1) * 32, buf ^ 1);
            asm volatile("cp.async.wait_group 1;");
        } else {
            asm volatile("cp.async.wait_group 0;");
        }
        __syncthreads();

        uint32_t base = sb + buf * 49152;

#pragma unroll
        for (int s = 0; s < 2; s++) {
            uint32_t a_f[4][4], b_hi[4][4], b_lo[4][4];
            int a_roff = (wr * 64 + (lane & 15)) * 48 + (lane >> 4) * 16 + s * 12288;
#pragma unroll
            for (int mt = 0; mt < 4; mt++)
                ldsm4(a_f[mt], base + a_roff + mt * 768);
            int q = lane >> 3, rl = lane & 7;
            int b_roff = (wc * 64 + (q >> 1) * 8 + rl) * 48 + (q & 1) * 16 + s * 6144;
#pragma unroll
            for (int p = 0; p < 4; p++) {
                ldsm4(b_hi[p], base + 24576 + b_roff + p * 768);
                ldsm4(b_lo[p], base + 36864 + b_roff + p * 768);
            }
#pragma unroll
            for (int mt = 0; mt < 4; mt++) {
#pragma unroll
                for (int nt = 0; nt < 8; nt++) {
                    const uint32_t* bh = &b_hi[nt >> 1][(nt & 1) * 2];
                    const uint32_t* bl = &b_lo[nt >> 1][(nt & 1) * 2];
                    mma_fp16(acc[mt][nt], a_f[mt], bh);
                    mma_fp16(acc[mt][nt], a_f[mt], bl);
                }
            }
        }
        __syncthreads();
    }
#undef COPY_CHUNK

    // ---- epilogue: smem transpose -> fp16 hi/lo [n][node] (coalesced) ----
    const int frow = lane >> 2, fcol = (lane & 3) * 2;
    float* Ct = (float*)smem;          // [128][264] fp32 = 135168B
    __syncthreads();
#pragma unroll
    for (int mt = 0; mt < 4; mt++) {
#pragma unroll
        for (int nt = 0; nt < 8; nt++) {
            int mloc = wr * 64 + mt * 16 + frow;
            int nloc = wc * 64 + nt * 8 + fcol;
            Ct[(nloc + 0) * 264 + mloc]     = acc[mt][nt][0];
            Ct[(nloc + 1) * 264 + mloc]     = acc[mt][nt][1];
            Ct[(nloc + 0) * 264 + mloc + 8] = acc[mt][nt][2];
            Ct[(nloc + 1) * 264 + mloc + 8] = acc[mt][nt][3];
        }
    }
    __syncthreads();
    for (int it = 0; it < 16; it++) {
        int nloc = it * 8 + wid;
#pragma unroll
        for (int j = 0; j < 2; j++) {
            int mloc = lane * 4 + j * 128;
            float4 v = *(float4*)&Ct[nloc * 264 + mloc];
            __half hi[4], lo[4];
            split_fp16(v.x, hi[0], lo[0]);
            split_fp16(v.y, hi[1], lo[1]);
            split_fp16(v.z, hi[2], lo[2]);
            split_fp16(v.w, hi[3], lo[3]);
            size_t off = (size_t)(n0 + nloc) * N_NODES + m0 + mloc;
            *(uint2*)(CThi + off) = *(uint2*)hi;
            *(uint2*)(CTlo + off) = *(uint2*)lo;
        }
    }
}

// ---------------- K4: gate = sigmoid([X0,X1,Y2]@Wg') ; build C0, r ---------
// Inputs from T arrays (hi+lo fp16). FFMA2 over row pairs.
__global__ void __launch_bounds__(128)
gate_kernel(const float* __restrict__ x, const float* __restrict__ st,
            const float* __restrict__ bg) {
    __shared__ float in_s[IN3][18];    // stride 18 floats (8B-aligned pairs)
    int row0 = blockIdx.x * 16;
    int b = row0 >> 11, n0 = row0 & 2047;
    int t = threadIdx.x;

    const __half* hiP[3] = { g_T0hi, g_T1hi, g_T2hi };
    const __half* loP[3] = { g_T0lo, g_T1lo, g_T2lo };

    for (int idx = t; idx < 16 * IN3; idx += 128) {
        int rr = idx & 15, i = idx >> 4;
        int k = i / C_IN, c = i - k * C_IN;
        size_t addr = (size_t)(b * C_IN + c) * N_NODES + n0 + rr;
        in_s[i][rr] = __half2float(hiP[k][addr]) + __half2float(loP[k][addr]);
    }
    __syncthreads();

    int o = t;
    unsigned long long acc2[8];
#pragma unroll
    for (int pp = 0; pp < 8; pp++) acc2[pp] = 0ULL;
    for (int i = 0; i < IN3; i++) {
        unsigned long long wd = pack_dup(g_Wg2[i * GATE_OUT + o]);
#pragma unroll
        for (int pp = 0; pp < 8; pp++)
            ffma2(acc2[pp], *(const unsigned long long*)&in_s[i][pp * 2], wd);
    }
    float bias = bg[o];
#pragma unroll
    for (int pp = 0; pp < 8; pp++) {
        float2 f = *(float2*)&acc2[pp];
#pragma unroll
        for (int h = 0; h < 2; h++) {
            int rr = pp * 2 + h;
            int row = row0 + rr, n = n0 + rr;
            float v = 1.0f / (1.0f + expf(-((h ? f.y : f.x) + bias)));
            if (o < 64) {
                float sv = st[row * 64 + o];
                g_P[n * BC + b * C_IN + 2 + o] = v * sv;        // z * state
                if (o < 2) g_P[n * BC + b * C_IN + o] = x[row * 2 + o];
            } else {
                g_r[row * 64 + (o - 64)] = v;                    // r gate
            }
        }
    }
}

// ---------------- K5: update = tanh([C0,C1,Y4]@Wu') ; GRU blend ------------
__global__ void __launch_bounds__(128)
update_kernel(const float* __restrict__ st, const float* __restrict__ bu,
              float* __restrict__ out) {
    __shared__ float in_s[IN3][18];
    int row0 = blockIdx.x * 16;
    int b = row0 >> 11, n0 = row0 & 2047;
    int t = threadIdx.x;

    const __half* hiP[3] = { g_T0hi, g_T1hi, g_T2hi };
    const __half* loP[3] = { g_T0lo, g_T1lo, g_T2lo };

    for (int idx = t; idx < 16 * IN3; idx += 128) {
        int rr = idx & 15, i = idx >> 4;
        int k = i / C_IN, c = i - k * C_IN;
        size_t addr = (size_t)(b * C_IN + c) * N_NODES + n0 + rr;
        in_s[i][rr] = __half2float(hiP[k][addr]) + __half2float(loP[k][addr]);
    }
    __syncthreads();

    int o = t & 63, hh = t >> 6;
    unsigned long long acc2[4];
#pragma unroll
    for (int pp = 0; pp < 4; pp++) acc2[pp] = 0ULL;
    for (int i = 0; i < IN3; i++) {
        unsigned long long wd = pack_dup(g_Wu2[i * UPD_OUT + o]);
#pragma unroll
        for (int pp = 0; pp < 4; pp++)
            ffma2(acc2[pp], *(const unsigned long long*)&in_s[i][hh * 8 + pp * 2], wd);
    }
    float bias = bu[o];
#pragma unroll
    for (int pp = 0; pp < 4; pp++) {
        float2 f = *(float2*)&acc2[pp];
#pragma unroll
        for (int h = 0; h < 2; h++) {
            int row = row0 + hh * 8 + pp * 2 + h;
            float hc = tanhf((h ? f.y : f.x) + bias);
            float rv = g_r[row * 64 + o];
            float sv = st[row * 64 + o];
            out[row * 64 + o] = rv * sv + (1.0f - rv) * hc;
        }
    }
}

// ---------------- launch ----------------------------------------------------
extern "C" void kernel_launch(void* const* d_in, const int* in_sizes, int n_in,
                              void* d_out, int out_size) {
    const float* x  = (const float*)d_in[0];
    const float* st = (const float*)d_in[1];
    const float* E  = (const float*)d_in[2];
    const float* Wg = (const float*)d_in[3];
    const float* bg = (const float*)d_in[4];
    const float* Wu = (const float*)d_in[5];
    const float* bu = (const float*)d_in[6];
    float* out = (float*)d_out;

    __half *pAh, *pT0hi, *pT0lo, *pT1hi, *pT1lo, *pT2hi, *pT2lo;
    float *pP;
    cudaGetSymbolAddress((void**)&pAh,   g_Ah);
    cudaGetSymbolAddress((void**)&pT0hi, g_T0hi);
    cudaGetSymbolAddress((void**)&pT0lo, g_T0lo);
    cudaGetSymbolAddress((void**)&pT1hi, g_T1hi);
    cudaGetSymbolAddress((void**)&pT1lo, g_T1lo);
    cudaGetSymbolAddress((void**)&pT2hi, g_T2hi);
    cudaGetSymbolAddress((void**)&pT2lo, g_T2lo);
    cudaGetSymbolAddress((void**)&pP,    g_P);

    const int SMEM_BYTES = 135168;   // max(2*49152 mainloop, epilogue Ct)
    cudaFuncSetAttribute(mma_gemm, cudaFuncAttributeMaxDynamicSharedMemorySize, SMEM_BYTES);

    dim3 gg(NPAD / 128, N_NODES / 256);   // (17, 8) = 136 CTAs, single wave
    dim3 tg(NPAD / 64, N_NODES / 64);     // (34, 32) transpose tiles

    supports_kernel<<<N_NODES, 256>>>(E);
    pack_kernel<<<N_NODES, 256>>>(x, st);
    wfold_kernel<<<(C_IN * GATE_OUT + 255) / 256, 256>>>(Wg, Wu);
    transpose_split_kernel<<<tg, 256>>>(pP, pT0hi, pT0lo);      // X0T

    // gate gconv (folded): X1T = (A X0)T ; Y2T = (A X1)T
    mma_gemm<<<gg, 256, SMEM_BYTES>>>(pAh, pT0hi, pT0lo, pT1hi, pT1lo);
    mma_gemm<<<gg, 256, SMEM_BYTES>>>(pAh, pT1hi, pT1lo, pT2hi, pT2lo);

    gate_kernel<<<(BATCH * N_NODES) / 16, 128>>>(x, st, bg);
    transpose_split_kernel<<<tg, 256>>>(pP, pT0hi, pT0lo);      // C0T

    // update gconv (folded): C1T = (A C0)T ; Y4T = (A C1)T
    mma_gemm<<<gg, 256, SMEM_BYTES>>>(pAh, pT0hi, pT0lo, pT1hi, pT1lo);
    mma_gemm<<<gg, 256, SMEM_BYTES>>>(pAh, pT1hi, pT1lo, pT2hi, pT2lo);

    update_kernel<<<(BATCH * N_NODES) / 16, 128>>>(st, bu, out);
}

// round 12
// speedup vs baseline: 1.3721x; 1.3721x over previous
#include <cuda_runtime.h>
#include <cuda_fp16.h>
#include <math.h>
#include <stdint.h>

#define N_NODES 2048
#define BATCH   32
#define HIDDEN  64
#define C_IN    66                 // DIM_IN + HIDDEN
#define BC      2112               // BATCH * C_IN
#define NPAD    2176               // BC padded to multiple of 128
#define IN3     198                // 3 * C_IN
#define GATE_OUT 128
#define UPD_OUT  64

// ---------------- device scratch (static: no allocations allowed) ----------
__device__ __half g_Ah [N_NODES * N_NODES];
__device__ __half g_T0 [NPAD * N_NODES];    // X0T / C0T
__device__ __half g_T1 [NPAD * N_NODES];    // X1T / C1T
__device__ __half g_T2 [NPAD * N_NODES];    // Y2T / Y4T (raw A@X1 / A@C1)
__device__ float g_P [N_NODES * BC];        // X0 fp32, then C0 fp32
__device__ float g_r [BATCH * N_NODES * HIDDEN];
__device__ float g_Wg2[IN3 * GATE_OUT];     // folded gate weights
__device__ float g_Wu2[IN3 * UPD_OUT];      // folded update weights

__device__ __forceinline__ uint32_t smem_to_u32(const void* p) {
    uint32_t a;
    asm("{ .reg .u64 t; cvta.to.shared.u64 t, %1; cvt.u32.u64 %0, t; }" : "=r"(a) : "l"(p));
    return a;
}
__device__ __forceinline__ void mma_fp16(float* c, const uint32_t* a, const uint32_t* b) {
    asm volatile(
        "mma.sync.aligned.m16n8k16.row.col.f32.f16.f16.f32 "
        "{%0,%1,%2,%3}, {%4,%5,%6,%7}, {%8,%9}, {%0,%1,%2,%3};"
        : "+f"(c[0]), "+f"(c[1]), "+f"(c[2]), "+f"(c[3])
        : "r"(a[0]), "r"(a[1]), "r"(a[2]), "r"(a[3]), "r"(b[0]), "r"(b[1]));
}
__device__ __forceinline__ void ldsm4(uint32_t* r, uint32_t addr) {
    asm volatile("ldmatrix.sync.aligned.m8n8.x4.shared.b16 {%0,%1,%2,%3}, [%4];"
                 : "=r"(r[0]), "=r"(r[1]), "=r"(r[2]), "=r"(r[3]) : "r"(addr));
}
__device__ __forceinline__ void cp16(uint32_t daddr, const void* g) {
    asm volatile("cp.async.cg.shared.global [%0], [%1], 16;" :: "r"(daddr), "l"(g));
}
__device__ __forceinline__ unsigned long long pack_dup(float b) {
    unsigned long long r;
    asm("mov.b64 %0, {%1, %1};" : "=l"(r) : "f"(b));
    return r;
}
__device__ __forceinline__ void ffma2(unsigned long long& d,
                                      unsigned long long a,
                                      unsigned long long b) {
    asm("fma.rn.f32x2 %0, %1, %2, %0;" : "+l"(d) : "l"(a), "l"(b));
}

// ---------------- K1: supports = softmax(relu(E E^T)) -> fp16 --------------
__global__ void supports_kernel(const float* __restrict__ E) {
    int n = blockIdx.x;
    int t = threadIdx.x;
    float e[10];
#pragma unroll
    for (int c = 0; c < 10; c++) e[c] = E[n * 10 + c];

    float vals[8];
    float vmax = 0.0f;
#pragma unroll
    for (int j = 0; j < 8; j++) {
        int m = j * 256 + t;
        float s = 0.0f;
#pragma unroll
        for (int c = 0; c < 10; c++) s = fmaf(e[c], E[m * 10 + c], s);
        s = fmaxf(s, 0.0f);
        vals[j] = s;
        vmax = fmaxf(vmax, s);
    }
    __shared__ float red[256];
    red[t] = vmax; __syncthreads();
    for (int s = 128; s > 0; s >>= 1) {
        if (t < s) red[t] = fmaxf(red[t], red[t + s]);
        __syncthreads();
    }
    vmax = red[0]; __syncthreads();

    float lsum = 0.0f;
#pragma unroll
    for (int j = 0; j < 8; j++) { vals[j] = expf(vals[j] - vmax); lsum += vals[j]; }
    red[t] = lsum; __syncthreads();
    for (int s = 128; s > 0; s >>= 1) {
        if (t < s) red[t] += red[t + s];
        __syncthreads();
    }
    float inv = 1.0f / red[0];
#pragma unroll
    for (int j = 0; j < 8; j++)
        g_Ah[(size_t)n * N_NODES + j * 256 + t] = __float2half_rn(vals[j] * inv);
}

// ---------------- K2: pack X0 fp32 [node][bc] (coalesced) ------------------
__global__ void pack_kernel(const float* __restrict__ x, const float* __restrict__ st) {
    int n = blockIdx.x;
    for (int i = threadIdx.x; i < BC; i += blockDim.x) {
        int b = i / C_IN, c = i - b * C_IN;
        float v = (c < 2) ? x[(b * N_NODES + n) * 2 + c]
                          : st[(b * N_NODES + n) * 64 + (c - 2)];
        g_P[n * BC + i] = v;
    }
}

// ---------------- K2b: fold Chebyshev into weights -------------------------
// W'0 = W0 - W2 ; W'1 = W1 ; W'2 = 2*W2   (so [X0,X1,2AX1-X0]W == [X0,X1,AX1]W')
__global__ void wfold_kernel(const float* __restrict__ Wg, const float* __restrict__ Wu) {
    int idx = blockIdx.x * 256 + threadIdx.x;
    if (idx < C_IN * GATE_OUT) {
        int c = idx / GATE_OUT, o = idx - c * GATE_OUT;
        float w0 = Wg[(c)            * GATE_OUT + o];
        float w1 = Wg[(C_IN + c)     * GATE_OUT + o];
        float w2 = Wg[(2 * C_IN + c) * GATE_OUT + o];
        g_Wg2[(c)            * GATE_OUT + o] = w0 - w2;
        g_Wg2[(C_IN + c)     * GATE_OUT + o] = w1;
        g_Wg2[(2 * C_IN + c) * GATE_OUT + o] = 2.f * w2;
    }
    if (idx < C_IN * UPD_OUT) {
        int c = idx / UPD_OUT, o = idx - c * UPD_OUT;
        float w0 = Wu[(c)            * UPD_OUT + o];
        float w1 = Wu[(C_IN + c)     * UPD_OUT + o];
        float w2 = Wu[(2 * C_IN + c) * UPD_OUT + o];
        g_Wu2[(c)            * UPD_OUT + o] = w0 - w2;
        g_Wu2[(C_IN + c)     * UPD_OUT + o] = w1;
        g_Wu2[(2 * C_IN + c) * UPD_OUT + o] = 2.f * w2;
    }
}

// ---------------- K3: tiled transpose: src[N][BC] fp32 -> dst[NPAD][N] fp16 -
__global__ void __launch_bounds__(256)
transpose_kernel(const float* __restrict__ src, __half* __restrict__ dst) {
    __shared__ float tile[64][65];
    int i0 = blockIdx.x * 64;
    int n0 = blockIdx.y * 64;
    int t = threadIdx.x;
    int iloc = t >> 2;
    int seg  = (t & 3) * 16;

    if (i0 < BC) {
        int nloc = t >> 2;
#pragma unroll
        for (int g = 0; g < 4; g++) {
            float4 v = *(const float4*)(src + (size_t)(n0 + nloc) * BC + i0 + seg + g * 4);
            tile[seg + g * 4 + 0][nloc] = v.x;
            tile[seg + g * 4 + 1][nloc] = v.y;
            tile[seg + g * 4 + 2][nloc] = v.z;
            tile[seg + g * 4 + 3][nloc] = v.w;
        }
        __syncthreads();
        __half h[16];
#pragma unroll
        for (int g = 0; g < 16; g++)
            h[g] = __float2half_rn(tile[iloc][seg + g]);
        size_t off = (size_t)(i0 + iloc) * N_NODES + n0 + seg;
        *(uint4*)(dst + off)     = *(uint4*)&h[0];
        *(uint4*)(dst + off + 8) = *(uint4*)&h[8];
    } else {
        uint4 z = make_uint4(0, 0, 0, 0);
        size_t off = (size_t)(i0 + iloc) * N_NODES + n0 + seg;
        *(uint4*)(dst + off)     = z;
        *(uint4*)(dst + off + 8) = z;
    }
}

// ---------------- HMMA GEMM: raw D = A @ B^T, fp16 in, fp16 T out ----------
// Single fp16 term, fp32 acc. CTA 256x128, 8 warps 64x64, BK=32, dbl buffer.
// smem per buffer (36864B): A@0 (2 slices x 12288), B@24576 (2 x 6144).
__global__ void __launch_bounds__(256, 1)
mma_gemm(const __half* __restrict__ Ah, const __half* __restrict__ B,
         __half* __restrict__ CT) {
    extern __shared__ char smem[];
    const uint32_t sb = smem_to_u32(smem);
    const int tid = threadIdx.x, wid = tid >> 5, lane = tid & 31;
    const int wr = wid >> 1, wc = wid & 1;            // warp tile: 64x64
    const int m0 = blockIdx.y * 256, n0 = blockIdx.x * 128;

    const __half* srcA = Ah + (size_t)m0 * N_NODES;
    const __half* srcB = B  + (size_t)n0 * N_NODES;

    float acc[4][8][4];
#pragma unroll
    for (int i = 0; i < 4; i++)
#pragma unroll
        for (int j = 0; j < 8; j++)
#pragma unroll
            for (int k = 0; k < 4; k++) acc[i][j][k] = 0.f;

#define COPY_CHUNK(k0, bufi) do {                                             \
        uint32_t _b = sb + (bufi) * 36864;                                    \
        _Pragma("unroll")                                                     \
        for (int _u = 0; _u < 4; _u++) {          /* A: 4 units */            \
            int _unit = _u * 256 + tid;                                       \
            int _row = _unit >> 2, _q = _unit & 3;                            \
            int _sl = _q >> 1, _hf = _q & 1;                                  \
            cp16(_b + _sl * 12288 + _row * 48 + _hf * 16,                     \
                 srcA + (size_t)_row * N_NODES + (k0) + _sl * 16 + _hf * 8);  \
        }                                                                     \
        _Pragma("unroll")                                                     \
        for (int _u = 0; _u < 2; _u++) {          /* B: 2 units */            \
            int _unit = _u * 256 + tid;                                       \
            int _row = _unit >> 2, _q = _unit & 3;                            \
            int _sl = _q >> 1, _hf = _q & 1;                                  \
            cp16(_b + 24576 + _sl * 6144 + _row * 48 + _hf * 16,              \
                 srcB + (size_t)_row * N_NODES + (k0) + _sl * 16 + _hf * 8);  \
        }                                                                     \
        asm volatile("cp.async.commit_group;");                               \
    } while (0)

    COPY_CHUNK(0, 0);

    const int NCHUNK = N_NODES / 32;   // 64
    for (int c = 0; c < NCHUNK; c++) {
        int buf = c & 1;
        if (c + 1 < NCHUNK) {
            COPY_CHUNK((c + 1) * 32, buf ^ 1);
            asm volatile("cp.async.wait_group 1;");
        } else {
            asm volatile("cp.async.wait_group 0;");
        }
        __syncthreads();

        uint32_t base = sb + buf * 36864;

#pragma unroll
        for (int s = 0; s < 2; s++) {
            uint32_t a_f[4][4], b_f[4][4];
            int a_roff = (wr * 64 + (lane & 15)) * 48 + (lane >> 4) * 16 + s * 12288;
#pragma unroll
            for (int mt = 0; mt < 4; mt++)
                ldsm4(a_f[mt], base + a_roff + mt * 768);
            int q = lane >> 3, rl = lane & 7;
            int b_roff = (wc * 64 + (q >> 1) * 8 + rl) * 48 + (q & 1) * 16 + s * 6144;
#pragma unroll
            for (int p = 0; p < 4; p++)
                ldsm4(b_f[p], base + 24576 + b_roff + p * 768);
#pragma unroll
            for (int mt = 0; mt < 4; mt++)
#pragma unroll
                for (int nt = 0; nt < 8; nt++)
                    mma_fp16(acc[mt][nt], a_f[mt], &b_f[nt >> 1][(nt & 1) * 2]);
        }
        __syncthreads();
    }
#undef COPY_CHUNK

    // ---- epilogue: smem transpose -> fp16 [n][node] (coalesced) ----
    const int frow = lane >> 2, fcol = (lane & 3) * 2;
    float* Ct = (float*)smem;          // [128][264] fp32 = 135168B
    __syncthreads();
#pragma unroll
    for (int mt = 0; mt < 4; mt++) {
#pragma unroll
        for (int nt = 0; nt < 8; nt++) {
            int mloc = wr * 64 + mt * 16 + frow;
            int nloc = wc * 64 + nt * 8 + fcol;
            Ct[(nloc + 0) * 264 + mloc]     = acc[mt][nt][0];
            Ct[(nloc + 1) * 264 + mloc]     = acc[mt][nt][1];
            Ct[(nloc + 0) * 264 + mloc + 8] = acc[mt][nt][2];
            Ct[(nloc + 1) * 264 + mloc + 8] = acc[mt][nt][3];
        }
    }
    __syncthreads();
    for (int it = 0; it < 16; it++) {
        int nloc = it * 8 + wid;
#pragma unroll
        for (int j = 0; j < 2; j++) {
            int mloc = lane * 4 + j * 128;
            float4 v = *(float4*)&Ct[nloc * 264 + mloc];
            __half h[4];
            h[0] = __float2half_rn(v.x);
            h[1] = __float2half_rn(v.y);
            h[2] = __float2half_rn(v.z);
            h[3] = __float2half_rn(v.w);
            size_t off = (size_t)(n0 + nloc) * N_NODES + m0 + mloc;
            *(uint2*)(CT + off) = *(uint2*)h;
        }
    }
}

// ---------------- K4: gate = sigmoid([X0,X1,Y2]@Wg') ; build C0, r ---------
__global__ void __launch_bounds__(128)
gate_kernel(const float* __restrict__ x, const float* __restrict__ st,
            const float* __restrict__ bg) {
    __shared__ float in_s[IN3][18];    // stride 18 floats (8B-aligned pairs)
    int row0 = blockIdx.x * 16;
    int b = row0 >> 11, n0 = row0 & 2047;
    int t = threadIdx.x;

    const __half* TP[3] = { g_T0, g_T1, g_T2 };

    for (int idx = t; idx < 16 * IN3; idx += 128) {
        int rr = idx & 15, i = idx >> 4;
        int k = i / C_IN, c = i - k * C_IN;
        in_s[i][rr] = __half2float(TP[k][(size_t)(b * C_IN + c) * N_NODES + n0 + rr]);
    }
    __syncthreads();

    int o = t;
    unsigned long long acc2[8];
#pragma unroll
    for (int pp = 0; pp < 8; pp++) acc2[pp] = 0ULL;
    for (int i = 0; i < IN3; i++) {
        unsigned long long wd = pack_dup(g_Wg2[i * GATE_OUT + o]);
#pragma unroll
        for (int pp = 0; pp < 8; pp++)
            ffma2(acc2[pp], *(const unsigned long long*)&in_s[i][pp * 2], wd);
    }
    float bias = bg[o];
#pragma unroll
    for (int pp = 0; pp < 8; pp++) {
        float2 f = *(float2*)&acc2[pp];
#pragma unroll
        for (int h = 0; h < 2; h++) {
            int rr = pp * 2 + h;
            int row = row0 + rr, n = n0 + rr;
            float v = 1.0f / (1.0f + expf(-((h ? f.y : f.x) + bias)));
            if (o < 64) {
                float sv = st[row * 64 + o];
                g_P[n * BC + b * C_IN + 2 + o] = v * sv;        // z * state
                if (o < 2) g_P[n * BC + b * C_IN + o] = x[row * 2 + o];
            } else {
                g_r[row * 64 + (o - 64)] = v;                    // r gate
            }
        }
    }
}

// ---------------- K5: update = tanh([C0,C1,Y4]@Wu') ; GRU blend ------------
__global__ void __launch_bounds__(128)
update_kernel(const float* __restrict__ st, const float* __restrict__ bu,
              float* __restrict__ out) {
    __shared__ float in_s[IN3][18];
    int row0 = blockIdx.x * 16;
    int b = row0 >> 11, n0 = row0 & 2047;
    int t = threadIdx.x;

    const __half* TP[3] = { g_T0, g_T1, g_T2 };

    for (int idx = t; idx < 16 * IN3; idx += 128) {
        int rr = idx & 15, i = idx >> 4;
        int k = i / C_IN, c = i - k * C_IN;
        in_s[i][rr] = __half2float(TP[k][(size_t)(b * C_IN + c) * N_NODES + n0 + rr]);
    }
    __syncthreads();

    int o = t & 63, hh = t >> 6;
    unsigned long long acc2[4];
#pragma unroll
    for (int pp = 0; pp < 4; pp++) acc2[pp] = 0ULL;
    for (int i = 0; i < IN3; i++) {
        unsigned long long wd = pack_dup(g_Wu2[i * UPD_OUT + o]);
#pragma unroll
        for (int pp = 0; pp < 4; pp++)
            ffma2(acc2[pp], *(const unsigned long long*)&in_s[i][hh * 8 + pp * 2], wd);
    }
    float bias = bu[o];
#pragma unroll
    for (int pp = 0; pp < 4; pp++) {
        float2 f = *(float2*)&acc2[pp];
#pragma unroll
        for (int h = 0; h < 2; h++) {
            int row = row0 + hh * 8 + pp * 2 + h;
            float hc = tanhf((h ? f.y : f.x) + bias);
            float rv = g_r[row * 64 + o];
            float sv = st[row * 64 + o];
            out[row * 64 + o] = rv * sv + (1.0f - rv) * hc;
        }
    }
}

// ---------------- launch ----------------------------------------------------
extern "C" void kernel_launch(void* const* d_in, const int* in_sizes, int n_in,
                              void* d_out, int out_size) {
    const float* x  = (const float*)d_in[0];
    const float* st = (const float*)d_in[1];
    const float* E  = (const float*)d_in[2];
    const float* Wg = (const float*)d_in[3];
    const float* bg = (const float*)d_in[4];
    const float* Wu = (const float*)d_in[5];
    const float* bu = (const float*)d_in[6];
    float* out = (float*)d_out;

    __half *pAh, *pT0, *pT1, *pT2;
    float *pP;
    cudaGetSymbolAddress((void**)&pAh, g_Ah);
    cudaGetSymbolAddress((void**)&pT0, g_T0);
    cudaGetSymbolAddress((void**)&pT1, g_T1);
    cudaGetSymbolAddress((void**)&pT2, g_T2);
    cudaGetSymbolAddress((void**)&pP,  g_P);

    const int SMEM_BYTES = 135168;   // max(2*36864 mainloop, epilogue Ct)
    cudaFuncSetAttribute(mma_gemm, cudaFuncAttributeMaxDynamicSharedMemorySize, SMEM_BYTES);

    dim3 gg(NPAD / 128, N_NODES / 256);   // (17, 8) = 136 CTAs, single wave
    dim3 tg(NPAD / 64, N_NODES / 64);     // (34, 32) transpose tiles

    supports_kernel<<<N_NODES, 256>>>(E);
    pack_kernel<<<N_NODES, 256>>>(x, st);
    wfold_kernel<<<(C_IN * GATE_OUT + 255) / 256, 256>>>(Wg, Wu);
    transpose_kernel<<<tg, 256>>>(pP, pT0);        // X0T

    // gate gconv (folded): X1T = (A X0)T ; Y2T = (A X1)T
    mma_gemm<<<gg, 256, SMEM_BYTES>>>(pAh, pT0, pT1);
    mma_gemm<<<gg, 256, SMEM_BYTES>>>(pAh, pT1, pT2);

    gate_kernel<<<(BATCH * N_NODES) / 16, 128>>>(x, st, bg);
    transpose_kernel<<<tg, 256>>>(pP, pT0);        // C0T

    // update gconv (folded): C1T = (A C0)T ; Y4T = (A C1)T
    mma_gemm<<<gg, 256, SMEM_BYTES>>>(pAh, pT0, pT1);
    mma_gemm<<<gg, 256, SMEM_BYTES>>>(pAh, pT1, pT2);

    update_kernel<<<(BATCH * N_NODES) / 16, 128>>>(st, bu, out);
}

// round 13
// speedup vs baseline: 1.4103x; 1.0278x over previous
#include <cuda_runtime.h>
#include <cuda_fp16.h>
#include <math.h>
#include <stdint.h>

#define N_NODES 2048
#define BATCH   32
#define HIDDEN  64
#define C_IN    66                 // DIM_IN + HIDDEN
#define BC      2112               // BATCH * C_IN
#define NPAD    2176               // BC padded to multiple of 128
#define IN3     198                // 3 * C_IN
#define GATE_OUT 128
#define UPD_OUT  64

// ---------------- device scratch (static: no allocations allowed) ----------
__device__ __half g_Ah [N_NODES * N_NODES];
__device__ __half g_T0 [NPAD * N_NODES];    // X0T, then (in-place) C0T
__device__ __half g_T1 [NPAD * N_NODES];    // X1T / C1T
__device__ __half g_T2 [NPAD * N_NODES];    // Y2T / Y4T (raw A@X1 / A@C1)
__device__ float g_r [BATCH * N_NODES * HIDDEN];
__device__ float g_Wg2[IN3 * GATE_OUT];     // folded gate weights
__device__ float g_Wu2[IN3 * UPD_OUT];      // folded update weights

__device__ __forceinline__ uint32_t smem_to_u32(const void* p) {
    uint32_t a;
    asm("{ .reg .u64 t; cvta.to.shared.u64 t, %1; cvt.u32.u64 %0, t; }" : "=r"(a) : "l"(p));
    return a;
}
__device__ __forceinline__ void mma_fp16(float* c, const uint32_t* a, const uint32_t* b) {
    asm volatile(
        "mma.sync.aligned.m16n8k16.row.col.f32.f16.f16.f32 "
        "{%0,%1,%2,%3}, {%4,%5,%6,%7}, {%8,%9}, {%0,%1,%2,%3};"
        : "+f"(c[0]), "+f"(c[1]), "+f"(c[2]), "+f"(c[3])
        : "r"(a[0]), "r"(a[1]), "r"(a[2]), "r"(a[3]), "r"(b[0]), "r"(b[1]));
}
__device__ __forceinline__ void ldsm4(uint32_t* r, uint32_t addr) {
    asm volatile("ldmatrix.sync.aligned.m8n8.x4.shared.b16 {%0,%1,%2,%3}, [%4];"
                 : "=r"(r[0]), "=r"(r[1]), "=r"(r[2]), "=r"(r[3]) : "r"(addr));
}
__device__ __forceinline__ void cp16(uint32_t daddr, const void* g) {
    asm volatile("cp.async.cg.shared.global [%0], [%1], 16;" :: "r"(daddr), "l"(g));
}
__device__ __forceinline__ unsigned long long pack_dup(float b) {
    unsigned long long r;
    asm("mov.b64 %0, {%1, %1};" : "=l"(r) : "f"(b));
    return r;
}
__device__ __forceinline__ void ffma2(unsigned long long& d,
                                      unsigned long long a,
                                      unsigned long long b) {
    asm("fma.rn.f32x2 %0, %1, %2, %0;" : "+l"(d) : "l"(a), "l"(b));
}

// ---------------- K1: supports = softmax(relu(E E^T)) -> fp16 --------------
__global__ void supports_kernel(const float* __restrict__ E) {
    int n = blockIdx.x;
    int t = threadIdx.x;
    float e[10];
#pragma unroll
    for (int c = 0; c < 10; c++) e[c] = E[n * 10 + c];

    float vals[8];
    float vmax = 0.0f;
#pragma unroll
    for (int j = 0; j < 8; j++) {
        int m = j * 256 + t;
        float s = 0.0f;
#pragma unroll
        for (int c = 0; c < 10; c++) s = fmaf(e[c], E[m * 10 + c], s);
        s = fmaxf(s, 0.0f);
        vals[j] = s;
        vmax = fmaxf(vmax, s);
    }
    __shared__ float red[256];
    red[t] = vmax; __syncthreads();
    for (int s = 128; s > 0; s >>= 1) {
        if (t < s) red[t] = fmaxf(red[t], red[t + s]);
        __syncthreads();
    }
    vmax = red[0]; __syncthreads();

    float lsum = 0.0f;
#pragma unroll
    for (int j = 0; j < 8; j++) { vals[j] = expf(vals[j] - vmax); lsum += vals[j]; }
    red[t] = lsum; __syncthreads();
    for (int s = 128; s > 0; s >>= 1) {
        if (t < s) red[t] += red[t + s];
        __syncthreads();
    }
    float inv = 1.0f / red[0];
#pragma unroll
    for (int j = 0; j < 8; j++)
        g_Ah[(size_t)n * N_NODES + j * 256 + t] = __float2half_rn(vals[j] * inv);
}

// ---------------- K2: fold Chebyshev into weights --------------------------
// W'0 = W0 - W2 ; W'1 = W1 ; W'2 = 2*W2   (so [X0,X1,2AX1-X0]W == [X0,X1,AX1]W')
__global__ void wfold_kernel(const float* __restrict__ Wg, const float* __restrict__ Wu) {
    int idx = blockIdx.x * 256 + threadIdx.x;
    if (idx < C_IN * GATE_OUT) {
        int c = idx / GATE_OUT, o = idx - c * GATE_OUT;
        float w0 = Wg[(c)            * GATE_OUT + o];
        float w1 = Wg[(C_IN + c)     * GATE_OUT + o];
        float w2 = Wg[(2 * C_IN + c) * GATE_OUT + o];
        g_Wg2[(c)            * GATE_OUT + o] = w0 - w2;
        g_Wg2[(C_IN + c)     * GATE_OUT + o] = w1;
        g_Wg2[(2 * C_IN + c) * GATE_OUT + o] = 2.f * w2;
    }
    if (idx < C_IN * UPD_OUT) {
        int c = idx / UPD_OUT, o = idx - c * UPD_OUT;
        float w0 = Wu[(c)            * UPD_OUT + o];
        float w1 = Wu[(C_IN + c)     * UPD_OUT + o];
        float w2 = Wu[(2 * C_IN + c) * UPD_OUT + o];
        g_Wu2[(c)            * UPD_OUT + o] = w0 - w2;
        g_Wu2[(C_IN + c)     * UPD_OUT + o] = w1;
        g_Wu2[(2 * C_IN + c) * UPD_OUT + o] = 2.f * w2;
    }
}

// ---------------- K3: fused pack+transpose: x,state -> X0T fp16 ------------
// Block = (b, 16 nodes). Coalesced loads into smem tile, 32B-segment stores.
__global__ void __launch_bounds__(128)
packT_kernel(const float* __restrict__ x, const float* __restrict__ st) {
    __shared__ float tile[16][68];     // [rr][c] c in 0..65, padded stride
    int blk = blockIdx.x;              // 4096 = 32 b * 128 node-chunks
    int b = blk >> 7;
    int n0 = (blk & 127) * 16;
    int t = threadIdx.x;

    for (int idx = t; idx < 1024; idx += 128) {
        int rr = idx >> 6, c = idx & 63;
        tile[rr][2 + c] = st[((size_t)b * N_NODES + n0 + rr) * 64 + c];
    }
    if (t < 32) {
        int rr = t >> 1, c = t & 1;
        tile[rr][c] = x[((size_t)b * N_NODES + n0 + rr) * 2 + c];
    }
    __syncthreads();

    if (t < C_IN) {
        __half h[16];
#pragma unroll
        for (int rr = 0; rr < 16; rr++) h[rr] = __float2half_rn(tile[rr][t]);
        size_t off = (size_t)(b * C_IN + t) * N_NODES + n0;
        *(uint4*)(g_T0 + off)     = *(uint4*)&h[0];
        *(uint4*)(g_T0 + off + 8) = *(uint4*)&h[8];
    }
}

// ---------------- K3b: zero pad rows [BC..NPAD) of T0 ----------------------
__global__ void padT0_kernel() {
    int idx = blockIdx.x * 256 + threadIdx.x;   // 16384 uint4 = 131072 halves
    if (idx < (NPAD - BC) * N_NODES / 8) {
        size_t off = (size_t)BC * N_NODES + (size_t)idx * 8;
        *(uint4*)(g_T0 + off) = make_uint4(0, 0, 0, 0);
    }
}

// ---------------- HMMA GEMM: raw D = A @ B^T, fp16 in, fp16 T out ----------
// Single fp16 term, fp32 acc. CTA 256x128, 8 warps 64x64, BK=32, dbl buffer.
__global__ void __launch_bounds__(256, 1)
mma_gemm(const __half* __restrict__ Ah, const __half* __restrict__ B,
         __half* __restrict__ CT) {
    extern __shared__ char smem[];
    const uint32_t sb = smem_to_u32(smem);
    const int tid = threadIdx.x, wid = tid >> 5, lane = tid & 31;
    const int wr = wid >> 1, wc = wid & 1;            // warp tile: 64x64
    const int m0 = blockIdx.y * 256, n0 = blockIdx.x * 128;

    const __half* srcA = Ah + (size_t)m0 * N_NODES;
    const __half* srcB = B  + (size_t)n0 * N_NODES;

    float acc[4][8][4];
#pragma unroll
    for (int i = 0; i < 4; i++)
#pragma unroll
        for (int j = 0; j < 8; j++)
#pragma unroll
            for (int k = 0; k < 4; k++) acc[i][j][k] = 0.f;

#define COPY_CHUNK(k0, bufi) do {                                             \
        uint32_t _b = sb + (bufi) * 36864;                                    \
        _Pragma("unroll")                                                     \
        for (int _u = 0; _u < 4; _u++) {          /* A: 4 units */            \
            int _unit = _u * 256 + tid;                                       \
            int _row = _unit >> 2, _q = _unit & 3;                            \
            int _sl = _q >> 1, _hf = _q & 1;                                  \
            cp16(_b + _sl * 12288 + _row * 48 + _hf * 16,                     \
                 srcA + (size_t)_row * N_NODES + (k0) + _sl * 16 + _hf * 8);  \
        }                                                                     \
        _Pragma("unroll")                                                     \
        for (int _u = 0; _u < 2; _u++) {          /* B: 2 units */            \
            int _unit = _u * 256 + tid;                                       \
            int _row = _unit >> 2, _q = _unit & 3;                            \
            int _sl = _q >> 1, _hf = _q & 1;                                  \
            cp16(_b + 24576 + _sl * 6144 + _row * 48 + _hf * 16,              \
                 srcB + (size_t)_row * N_NODES + (k0) + _sl * 16 + _hf * 8);  \
        }                                                                     \
        asm volatile("cp.async.commit_group;");                               \
    } while (0)

    COPY_CHUNK(0, 0);

    const int NCHUNK = N_NODES / 32;   // 64
    for (int c = 0; c < NCHUNK; c++) {
        int buf = c & 1;
        if (c + 1 < NCHUNK) {
            COPY_CHUNK((c + 1) * 32, buf ^ 1);
            asm volatile("cp.async.wait_group 1;");
        } else {
            asm volatile("cp.async.wait_group 0;");
        }
        __syncthreads();

        uint32_t base = sb + buf * 36864;

#pragma unroll
        for (int s = 0; s < 2; s++) {
            uint32_t a_f[4][4], b_f[4][4];
            int a_roff = (wr * 64 + (lane & 15)) * 48 + (lane >> 4) * 16 + s * 12288;
#pragma unroll
            for (int mt = 0; mt < 4; mt++)
                ldsm4(a_f[mt], base + a_roff + mt * 768);
            int q = lane >> 3, rl = lane & 7;
            int b_roff = (wc * 64 + (q >> 1) * 8 + rl) * 48 + (q & 1) * 16 + s * 6144;
#pragma unroll
            for (int p = 0; p < 4; p++)
                ldsm4(b_f[p], base + 24576 + b_roff + p * 768);
#pragma unroll
            for (int mt = 0; mt < 4; mt++)
#pragma unroll
                for (int nt = 0; nt < 8; nt++)
                    mma_fp16(acc[mt][nt], a_f[mt], &b_f[nt >> 1][(nt & 1) * 2]);
        }
        __syncthreads();
    }
#undef COPY_CHUNK

    // ---- epilogue: smem transpose -> fp16 [n][node] (coalesced) ----
    const int frow = lane >> 2, fcol = (lane & 3) * 2;
    float* Ct = (float*)smem;          // [128][264] fp32 = 135168B
    __syncthreads();
#pragma unroll
    for (int mt = 0; mt < 4; mt++) {
#pragma unroll
        for (int nt = 0; nt < 8; nt++) {
            int mloc = wr * 64 + mt * 16 + frow;
            int nloc = wc * 64 + nt * 8 + fcol;
            Ct[(nloc + 0) * 264 + mloc]     = acc[mt][nt][0];
            Ct[(nloc + 1) * 264 + mloc]     = acc[mt][nt][1];
            Ct[(nloc + 0) * 264 + mloc + 8] = acc[mt][nt][2];
            Ct[(nloc + 1) * 264 + mloc + 8] = acc[mt][nt][3];
        }
    }
    __syncthreads();
    for (int it = 0; it < 16; it++) {
        int nloc = it * 8 + wid;
#pragma unroll
        for (int j = 0; j < 2; j++) {
            int mloc = lane * 4 + j * 128;
            float4 v = *(float4*)&Ct[nloc * 264 + mloc];
            __half h[4];
            h[0] = __float2half_rn(v.x);
            h[1] = __float2half_rn(v.y);
            h[2] = __float2half_rn(v.z);
            h[3] = __float2half_rn(v.w);
            size_t off = (size_t)(n0 + nloc) * N_NODES + m0 + mloc;
            *(uint2*)(CT + off) = *(uint2*)h;
        }
    }
}

// ---------------- K4: gate = sigmoid([X0,X1,Y2]@Wg') ; C0T in place --------
// Block reads exactly the T0 region it overwrites (same b, same 16 nodes);
// reads complete before __syncthreads, writes after -> race-free in place.
__global__ void __launch_bounds__(128)
gate_kernel(const float* __restrict__ x, const float* __restrict__ st,
            const float* __restrict__ bg) {
    __shared__ float in_s[IN3][18];    // stride 18 floats (8B-aligned pairs)
    int row0 = blockIdx.x * 16;
    int b = row0 >> 11, n0 = row0 & 2047;
    int t = threadIdx.x;

    const __half* TP[3] = { g_T0, g_T1, g_T2 };

    for (int idx = t; idx < 16 * IN3; idx += 128) {
        int rr = idx & 15, i = idx >> 4;
        int k = i / C_IN, c = i - k * C_IN;
        in_s[i][rr] = __half2float(TP[k][(size_t)(b * C_IN + c) * N_NODES + n0 + rr]);
    }
    __syncthreads();

    int o = t;
    unsigned long long acc2[8];
#pragma unroll
    for (int pp = 0; pp < 8; pp++) acc2[pp] = 0ULL;
    for (int i = 0; i < IN3; i++) {
        unsigned long long wd = pack_dup(g_Wg2[i * GATE_OUT + o]);
#pragma unroll
        for (int pp = 0; pp < 8; pp++)
            ffma2(acc2[pp], *(const unsigned long long*)&in_s[i][pp * 2], wd);
    }
    float bias = bg[o];
    __half c16[16];
#pragma unroll
    for (int pp = 0; pp < 8; pp++) {
        float2 f = *(float2*)&acc2[pp];
#pragma unroll
        for (int h = 0; h < 2; h++) {
            int rr = pp * 2 + h;
            int row = row0 + rr;
            float v = 1.0f / (1.0f + expf(-((h ? f.y : f.x) + bias)));
            if (o < 64) {
                c16[rr] = __float2half_rn(v * st[row * 64 + o]);    // z*state
            } else {
                g_r[row * 64 + (o - 64)] = v;                        // r gate
            }
        }
    }
    if (o < 64) {
        size_t off = (size_t)(b * C_IN + 2 + o) * N_NODES + n0;
        *(uint4*)(g_T0 + off)     = *(uint4*)&c16[0];
        *(uint4*)(g_T0 + off + 8) = *(uint4*)&c16[8];
        if (o < 2) {
            __half xh[16];
#pragma unroll
            for (int rr = 0; rr < 16; rr++)
                xh[rr] = __float2half_rn(x[(row0 + rr) * 2 + o]);
            size_t off2 = (size_t)(b * C_IN + o) * N_NODES + n0;
            *(uint4*)(g_T0 + off2)     = *(uint4*)&xh[0];
            *(uint4*)(g_T0 + off2 + 8) = *(uint4*)&xh[8];
        }
    }
}

// ---------------- K5: update = tanh([C0,C1,Y4]@Wu') ; GRU blend ------------
__global__ void __launch_bounds__(128)
update_kernel(const float* __restrict__ st, const float* __restrict__ bu,
              float* __restrict__ out) {
    __shared__ float in_s[IN3][18];
    int row0 = blockIdx.x * 16;
    int b = row0 >> 11, n0 = row0 & 2047;
    int t = threadIdx.x;

    const __half* TP[3] = { g_T0, g_T1, g_T2 };

    for (int idx = t; idx < 16 * IN3; idx += 128) {
        int rr = idx & 15, i = idx >> 4;
        int k = i / C_IN, c = i - k * C_IN;
        in_s[i][rr] = __half2float(TP[k][(size_t)(b * C_IN + c) * N_NODES + n0 + rr]);
    }
    __syncthreads();

    int o = t & 63, hh = t >> 6;
    unsigned long long acc2[4];
#pragma unroll
    for (int pp = 0; pp < 4; pp++) acc2[pp] = 0ULL;
    for (int i = 0; i < IN3; i++) {
        unsigned long long wd = pack_dup(g_Wu2[i * UPD_OUT + o]);
#pragma unroll
        for (int pp = 0; pp < 4; pp++)
            ffma2(acc2[pp], *(const unsigned long long*)&in_s[i][hh * 8 + pp * 2], wd);
    }
    float bias = bu[o];
#pragma unroll
    for (int pp = 0; pp < 4; pp++) {
        float2 f = *(float2*)&acc2[pp];
#pragma unroll
        for (int h = 0; h < 2; h++) {
            int row = row0 + hh * 8 + pp * 2 + h;
            float hc = tanhf((h ? f.y : f.x) + bias);
            float rv = g_r[row * 64 + o];
            float sv = st[row * 64 + o];
            out[row * 64 + o] = rv * sv + (1.0f - rv) * hc;
        }
    }
}

// ---------------- launch ----------------------------------------------------
extern "C" void kernel_launch(void* const* d_in, const int* in_sizes, int n_in,
                              void* d_out, int out_size) {
    const float* x  = (const float*)d_in[0];
    const float* st = (const float*)d_in[1];
    const float* E  = (const float*)d_in[2];
    const float* Wg = (const float*)d_in[3];
    const float* bg = (const float*)d_in[4];
    const float* Wu = (const float*)d_in[5];
    const float* bu = (const float*)d_in[6];
    float* out = (float*)d_out;

    __half *pAh, *pT0, *pT1, *pT2;
    cudaGetSymbolAddress((void**)&pAh, g_Ah);
    cudaGetSymbolAddress((void**)&pT0, g_T0);
    cudaGetSymbolAddress((void**)&pT1, g_T1);
    cudaGetSymbolAddress((void**)&pT2, g_T2);

    const int SMEM_BYTES = 135168;   // max(2*36864 mainloop, epilogue Ct)
    cudaFuncSetAttribute(mma_gemm, cudaFuncAttributeMaxDynamicSharedMemorySize, SMEM_BYTES);

    dim3 gg(NPAD / 128, N_NODES / 256);   // (17, 8) = 136 CTAs, single wave

    supports_kernel<<<N_NODES, 256>>>(E);
    wfold_kernel<<<(C_IN * GATE_OUT + 255) / 256, 256>>>(Wg, Wu);
    packT_kernel<<<BATCH * (N_NODES / 16), 128>>>(x, st);   // X0T directly
    padT0_kernel<<<64, 256>>>();

    // gate gconv (folded): X1T = (A X0)T ; Y2T = (A X1)T
    mma_gemm<<<gg, 256, SMEM_BYTES>>>(pAh, pT0, pT1);
    mma_gemm<<<gg, 256, SMEM_BYTES>>>(pAh, pT1, pT2);

    gate_kernel<<<(BATCH * N_NODES) / 16, 128>>>(x, st, bg);  // C0T in place

    // update gconv (folded): C1T = (A C0)T ; Y4T = (A C1)T
    mma_gemm<<<gg, 256, SMEM_BYTES>>>(pAh, pT0, pT1);
    mma_gemm<<<gg, 256, SMEM_BYTES>>>(pAh, pT1, pT2);

    update_kernel<<<(BATCH * N_NODES) / 16, 128>>>(st, bu, out);
}

// round 14
// speedup vs baseline: 1.4365x; 1.0186x over previous
#include <cuda_runtime.h>
#include <cuda_fp16.h>
#include <math.h>
#include <stdint.h>

#define N_NODES 2048
#define BATCH   32
#define HIDDEN  64
#define C_IN    66                 // DIM_IN + HIDDEN
#define BC      2112               // BATCH * C_IN
#define NPAD    2176               // BC padded to multiple of 128
#define IN3     198                // 3 * C_IN
#define GATE_OUT 128
#define UPD_OUT  64

// ---------------- device scratch (static: no allocations allowed) ----------
__device__ __half g_Ah [N_NODES * N_NODES];
__device__ __half g_T0 [NPAD * N_NODES];    // X0T, then (in-place) C0T
__device__ __half g_T1 [NPAD * N_NODES];    // X1T / C1T
__device__ __half g_T2 [NPAD * N_NODES];    // Y2T / Y4T
__device__ float g_r [BATCH * N_NODES * HIDDEN];
__device__ float g_Wg2[IN3 * GATE_OUT];     // folded gate weights
__device__ float g_Wu2[IN3 * UPD_OUT];      // folded update weights

__device__ __forceinline__ uint32_t smem_to_u32(const void* p) {
    uint32_t a;
    asm("{ .reg .u64 t; cvta.to.shared.u64 t, %1; cvt.u32.u64 %0, t; }" : "=r"(a) : "l"(p));
    return a;
}
__device__ __forceinline__ void mma_fp16(float* c, const uint32_t* a, const uint32_t* b) {
    asm volatile(
        "mma.sync.aligned.m16n8k16.row.col.f32.f16.f16.f32 "
        "{%0,%1,%2,%3}, {%4,%5,%6,%7}, {%8,%9}, {%0,%1,%2,%3};"
        : "+f"(c[0]), "+f"(c[1]), "+f"(c[2]), "+f"(c[3])
        : "r"(a[0]), "r"(a[1]), "r"(a[2]), "r"(a[3]), "r"(b[0]), "r"(b[1]));
}
__device__ __forceinline__ void ldsm4(uint32_t* r, uint32_t addr) {
    asm volatile("ldmatrix.sync.aligned.m8n8.x4.shared.b16 {%0,%1,%2,%3}, [%4];"
                 : "=r"(r[0]), "=r"(r[1]), "=r"(r[2]), "=r"(r[3]) : "r"(addr));
}
__device__ __forceinline__ void cp16(uint32_t daddr, const void* g) {
    asm volatile("cp.async.cg.shared.global [%0], [%1], 16;" :: "r"(daddr), "l"(g));
}
__device__ __forceinline__ unsigned long long pack_dup(float b) {
    unsigned long long r;
    asm("mov.b64 %0, {%1, %1};" : "=l"(r) : "f"(b));
    return r;
}
__device__ __forceinline__ void ffma2(unsigned long long& d,
                                      unsigned long long a,
                                      unsigned long long b) {
    asm("fma.rn.f32x2 %0, %1, %2, %0;" : "+l"(d) : "l"(a), "l"(b));
}

// ---------------- K1: fused prep: supports | packT | padT0 | wfold ---------
// blocks [0,2048)        : supports row n = blockIdx
// blocks [2048,4096)     : packT, (b, 32 nodes) per block
// blocks [4096,4160)     : padT0
// blocks [4160,4193)     : wfold
__global__ void __launch_bounds__(256)
prep_kernel(const float* __restrict__ E, const float* __restrict__ x,
            const float* __restrict__ st, const float* __restrict__ Wg,
            const float* __restrict__ Wu) {
    int blk = blockIdx.x;
    int t = threadIdx.x;

    if (blk < 2048) {                       // ---- supports ----
        int n = blk;
        float e[10];
#pragma unroll
        for (int c = 0; c < 10; c++) e[c] = E[n * 10 + c];
        float vals[8];
        float vmax = 0.0f;
#pragma unroll
        for (int j = 0; j < 8; j++) {
            int m = j * 256 + t;
            float s = 0.0f;
#pragma unroll
            for (int c = 0; c < 10; c++) s = fmaf(e[c], E[m * 10 + c], s);
            s = fmaxf(s, 0.0f);
            vals[j] = s;
            vmax = fmaxf(vmax, s);
        }
        __shared__ float red[256];
        red[t] = vmax; __syncthreads();
        for (int s = 128; s > 0; s >>= 1) {
            if (t < s) red[t] = fmaxf(red[t], red[t + s]);
            __syncthreads();
        }
        vmax = red[0]; __syncthreads();
        float lsum = 0.0f;
#pragma unroll
        for (int j = 0; j < 8; j++) { vals[j] = expf(vals[j] - vmax); lsum += vals[j]; }
        red[t] = lsum; __syncthreads();
        for (int s = 128; s > 0; s >>= 1) {
            if (t < s) red[t] += red[t + s];
            __syncthreads();
        }
        float inv = 1.0f / red[0];
#pragma unroll
        for (int j = 0; j < 8; j++)
            g_Ah[(size_t)n * N_NODES + j * 256 + t] = __float2half_rn(vals[j] * inv);

    } else if (blk < 4096) {                // ---- packT ----
        __shared__ float tile[2][16][68];
        int p = blk - 2048;                 // 2048 = 32 b * 64 chunks(32 nodes)
        int b = p >> 6;
        int n0 = (p & 63) * 32;
        int sub = t >> 7;                   // 0/1 -> 16-node half
        int t2 = t & 127;
        int nb = n0 + sub * 16;

        for (int idx = t2; idx < 1024; idx += 128) {
            int rr = idx >> 6, c = idx & 63;
            tile[sub][rr][2 + c] = st[((size_t)b * N_NODES + nb + rr) * 64 + c];
        }
        if (t2 < 32) {
            int rr = t2 >> 1, c = t2 & 1;
            tile[sub][rr][c] = x[((size_t)b * N_NODES + nb + rr) * 2 + c];
        }
        __syncthreads();
        if (t2 < C_IN) {
            __half h[16];
#pragma unroll
            for (int rr = 0; rr < 16; rr++) h[rr] = __float2half_rn(tile[sub][rr][t2]);
            size_t off = (size_t)(b * C_IN + t2) * N_NODES + nb;
            *(uint4*)(g_T0 + off)     = *(uint4*)&h[0];
            *(uint4*)(g_T0 + off + 8) = *(uint4*)&h[8];
        }

    } else if (blk < 4160) {                // ---- padT0 ----
        int idx = (blk - 4096) * 256 + t;   // 16384 uint4
        if (idx < (NPAD - BC) * N_NODES / 8) {
            size_t off = (size_t)BC * N_NODES + (size_t)idx * 8;
            *(uint4*)(g_T0 + off) = make_uint4(0, 0, 0, 0);
        }

    } else {                                // ---- wfold ----
        int idx = (blk - 4160) * 256 + t;
        if (idx < C_IN * GATE_OUT) {
            int c = idx / GATE_OUT, o = idx - c * GATE_OUT;
            float w0 = Wg[(c)            * GATE_OUT + o];
            float w1 = Wg[(C_IN + c)     * GATE_OUT + o];
            float w2 = Wg[(2 * C_IN + c) * GATE_OUT + o];
            g_Wg2[(c)            * GATE_OUT + o] = w0 - w2;
            g_Wg2[(C_IN + c)     * GATE_OUT + o] = w1;
            g_Wg2[(2 * C_IN + c) * GATE_OUT + o] = 2.f * w2;
        }
        if (idx < C_IN * UPD_OUT) {
            int c = idx / UPD_OUT, o = idx - c * UPD_OUT;
            float w0 = Wu[(c)            * UPD_OUT + o];
            float w1 = Wu[(C_IN + c)     * UPD_OUT + o];
            float w2 = Wu[(2 * C_IN + c) * UPD_OUT + o];
            g_Wu2[(c)            * UPD_OUT + o] = w0 - w2;
            g_Wu2[(C_IN + c)     * UPD_OUT + o] = w1;
            g_Wu2[(2 * C_IN + c) * UPD_OUT + o] = 2.f * w2;
        }
    }
}

// ---------------- HMMA GEMM: raw D = A @ B^T, fp16 in, fp16 T out ----------
// Single fp16 term, fp32 acc. CTA 256x128, 8 warps 64x64, BK=64, dbl buffer.
// smem per buffer (73728B): A@0 (4 k16-slices x 12288), B@49152 (4 x 6144).
__global__ void __launch_bounds__(256, 1)
mma_gemm(const __half* __restrict__ Ah, const __half* __restrict__ B,
         __half* __restrict__ CT) {
    extern __shared__ char smem[];
    const uint32_t sb = smem_to_u32(smem);
    const int tid = threadIdx.x, wid = tid >> 5, lane = tid & 31;
    const int wr = wid >> 1, wc = wid & 1;            // warp tile: 64x64
    const int m0 = blockIdx.y * 256, n0 = blockIdx.x * 128;

    const __half* srcA = Ah + (size_t)m0 * N_NODES;
    const __half* srcB = B  + (size_t)n0 * N_NODES;

    float acc[4][8][4];
#pragma unroll
    for (int i = 0; i < 4; i++)
#pragma unroll
        for (int j = 0; j < 8; j++)
#pragma unroll
            for (int k = 0; k < 4; k++) acc[i][j][k] = 0.f;

#define COPY_CHUNK(k0, bufi) do {                                             \
        uint32_t _b = sb + (bufi) * 73728;                                    \
        _Pragma("unroll")                                                     \
        for (int _u = 0; _u < 8; _u++) {          /* A: 8 units */            \
            int _unit = _u * 256 + tid;                                       \
            int _row = _unit >> 3, _q = _unit & 7;                            \
            int _sl = _q >> 1, _hf = _q & 1;                                  \
            cp16(_b + _sl * 12288 + _row * 48 + _hf * 16,                     \
                 srcA + (size_t)_row * N_NODES + (k0) + _sl * 16 + _hf * 8);  \
        }                                                                     \
        _Pragma("unroll")                                                     \
        for (int _u = 0; _u < 4; _u++) {          /* B: 4 units */            \
            int _unit = _u * 256 + tid;                                       \
            int _row = _unit >> 3, _q = _unit & 7;                            \
            int _sl = _q >> 1, _hf = _q & 1;                                  \
            cp16(_b + 49152 + _sl * 6144 + _row * 48 + _hf * 16,              \
                 srcB + (size_t)_row * N_NODES + (k0) + _sl * 16 + _hf * 8);  \
        }                                                                     \
        asm volatile("cp.async.commit_group;");                               \
    } while (0)

    COPY_CHUNK(0, 0);

    const int NCHUNK = N_NODES / 64;   // 32
    for (int c = 0; c < NCHUNK; c++) {
        int buf = c & 1;
        if (c + 1 < NCHUNK) {
            COPY_CHUNK((c + 1) * 64, buf ^ 1);
            asm volatile("cp.async.wait_group 1;");
        } else {
            asm volatile("cp.async.wait_group 0;");
        }
        __syncthreads();

        uint32_t base = sb + buf * 73728;

#pragma unroll
        for (int s = 0; s < 4; s++) {
            uint32_t a_f[4][4], b_f[4][4];
            int a_roff = (wr * 64 + (lane & 15)) * 48 + (lane >> 4) * 16 + s * 12288;
#pragma unroll
            for (int mt = 0; mt < 4; mt++)
                ldsm4(a_f[mt], base + a_roff + mt * 768);
            int q = lane >> 3, rl = lane & 7;
            int b_roff = (wc * 64 + (q >> 1) * 8 + rl) * 48 + (q & 1) * 16 + s * 6144;
#pragma unroll
            for (int p = 0; p < 4; p++)
                ldsm4(b_f[p], base + 49152 + b_roff + p * 768);
#pragma unroll
            for (int mt = 0; mt < 4; mt++)
#pragma unroll
                for (int nt = 0; nt < 8; nt++)
                    mma_fp16(acc[mt][nt], a_f[mt], &b_f[nt >> 1][(nt & 1) * 2]);
        }
        __syncthreads();
    }
#undef COPY_CHUNK

    // ---- epilogue: smem transpose -> fp16 [n][node] (coalesced) ----
    const int frow = lane >> 2, fcol = (lane & 3) * 2;
    float* Ct = (float*)smem;          // [128][264] fp32 = 135168B
    __syncthreads();
#pragma unroll
    for (int mt = 0; mt < 4; mt++) {
#pragma unroll
        for (int nt = 0; nt < 8; nt++) {
            int mloc = wr * 64 + mt * 16 + frow;
            int nloc = wc * 64 + nt * 8 + fcol;
            Ct[(nloc + 0) * 264 + mloc]     = acc[mt][nt][0];
            Ct[(nloc + 1) * 264 + mloc]     = acc[mt][nt][1];
            Ct[(nloc + 0) * 264 + mloc + 8] = acc[mt][nt][2];
            Ct[(nloc + 1) * 264 + mloc + 8] = acc[mt][nt][3];
        }
    }
    __syncthreads();
    for (int it = 0; it < 16; it++) {
        int nloc = it * 8 + wid;
#pragma unroll
        for (int j = 0; j < 2; j++) {
            int mloc = lane * 4 + j * 128;
            float4 v = *(float4*)&Ct[nloc * 264 + mloc];
            __half h[4];
            h[0] = __float2half_rn(v.x);
            h[1] = __float2half_rn(v.y);
            h[2] = __float2half_rn(v.z);
            h[3] = __float2half_rn(v.w);
            size_t off = (size_t)(n0 + nloc) * N_NODES + m0 + mloc;
            *(uint2*)(CT + off) = *(uint2*)h;
        }
    }
}

// ---------------- K4: gate = sigmoid([X0,X1,Y2]@Wg') ; C0T in place --------
__global__ void __launch_bounds__(128)
gate_kernel(const float* __restrict__ x, const float* __restrict__ st,
            const float* __restrict__ bg) {
    __shared__ float in_s[IN3][18];
    int row0 = blockIdx.x * 16;
    int b = row0 >> 11, n0 = row0 & 2047;
    int t = threadIdx.x;

    const __half* TP[3] = { g_T0, g_T1, g_T2 };

    for (int idx = t; idx < 16 * IN3; idx += 128) {
        int rr = idx & 15, i = idx >> 4;
        int k = i / C_IN, c = i - k * C_IN;
        in_s[i][rr] = __half2float(TP[k][(size_t)(b * C_IN + c) * N_NODES + n0 + rr]);
    }
    __syncthreads();

    int o = t;
    unsigned long long acc2[8];
#pragma unroll
    for (int pp = 0; pp < 8; pp++) acc2[pp] = 0ULL;
    for (int i = 0; i < IN3; i++) {
        unsigned long long wd = pack_dup(g_Wg2[i * GATE_OUT + o]);
#pragma unroll
        for (int pp = 0; pp < 8; pp++)
            ffma2(acc2[pp], *(const unsigned long long*)&in_s[i][pp * 2], wd);
    }
    float bias = bg[o];
    __half c16[16];
#pragma unroll
    for (int pp = 0; pp < 8; pp++) {
        float2 f = *(float2*)&acc2[pp];
#pragma unroll
        for (int h = 0; h < 2; h++) {
            int rr = pp * 2 + h;
            int row = row0 + rr;
            float v = 1.0f / (1.0f + expf(-((h ? f.y : f.x) + bias)));
            if (o < 64) {
                c16[rr] = __float2half_rn(v * st[row * 64 + o]);    // z*state
            } else {
                g_r[row * 64 + (o - 64)] = v;                        // r gate
            }
        }
    }
    if (o < 64) {
        size_t off = (size_t)(b * C_IN + 2 + o) * N_NODES + n0;
        *(uint4*)(g_T0 + off)     = *(uint4*)&c16[0];
        *(uint4*)(g_T0 + off + 8) = *(uint4*)&c16[8];
        if (o < 2) {
            __half xh[16];
#pragma unroll
            for (int rr = 0; rr < 16; rr++)
                xh[rr] = __float2half_rn(x[(row0 + rr) * 2 + o]);
            size_t off2 = (size_t)(b * C_IN + o) * N_NODES + n0;
            *(uint4*)(g_T0 + off2)     = *(uint4*)&xh[0];
            *(uint4*)(g_T0 + off2 + 8) = *(uint4*)&xh[8];
        }
    }
}

// ---------------- K5: update = tanh([C0,C1,Y4]@Wu') ; GRU blend ------------
__global__ void __launch_bounds__(128)
update_kernel(const float* __restrict__ st, const float* __restrict__ bu,
              float* __restrict__ out) {
    __shared__ float in_s[IN3][18];
    int row0 = blockIdx.x * 16;
    int b = row0 >> 11, n0 = row0 & 2047;
    int t = threadIdx.x;

    const __half* TP[3] = { g_T0, g_T1, g_T2 };

    for (int idx = t; idx < 16 * IN3; idx += 128) {
        int rr = idx & 15, i = idx >> 4;
        int k = i / C_IN, c = i - k * C_IN;
        in_s[i][rr] = __half2float(TP[k][(size_t)(b * C_IN + c) * N_NODES + n0 + rr]);
    }
    __syncthreads();

    int o = t & 63, hh = t >> 6;
    unsigned long long acc2[4];
#pragma unroll
    for (int pp = 0; pp < 4; pp++) acc2[pp] = 0ULL;
    for (int i = 0; i < IN3; i++) {
        unsigned long long wd = pack_dup(g_Wu2[i * UPD_OUT + o]);
#pragma unroll
        for (int pp = 0; pp < 4; pp++)
            ffma2(acc2[pp], *(const unsigned long long*)&in_s[i][hh * 8 + pp * 2], wd);
    }
    float bias = bu[o];
#pragma unroll
    for (int pp = 0; pp < 4; pp++) {
        float2 f = *(float2*)&acc2[pp];
#pragma unroll
        for (int h = 0; h < 2; h++) {
            int row = row0 + hh * 8 + pp * 2 + h;
            float hc = tanhf((h ? f.y : f.x) + bias);
            float rv = g_r[row * 64 + o];
            float sv = st[row * 64 + o];
            out[row * 64 + o] = rv * sv + (1.0f - rv) * hc;
        }
    }
}

// ---------------- launch ----------------------------------------------------
extern "C" void kernel_launch(void* const* d_in, const int* in_sizes, int n_in,
                              void* d_out, int out_size) {
    const float* x  = (const float*)d_in[0];
    const float* st = (const float*)d_in[1];
    const float* E  = (const float*)d_in[2];
    const float* Wg = (const float*)d_in[3];
    const float* bg = (const float*)d_in[4];
    const float* Wu = (const float*)d_in[5];
    const float* bu = (const float*)d_in[6];
    float* out = (float*)d_out;

    __half *pAh, *pT0, *pT1, *pT2;
    cudaGetSymbolAddress((void**)&pAh, g_Ah);
    cudaGetSymbolAddress((void**)&pT0, g_T0);
    cudaGetSymbolAddress((void**)&pT1, g_T1);
    cudaGetSymbolAddress((void**)&pT2, g_T2);

    const int SMEM_BYTES = 2 * 73728;   // 147456 (epilogue Ct uses 135168)
    cudaFuncSetAttribute(mma_gemm, cudaFuncAttributeMaxDynamicSharedMemorySize, SMEM_BYTES);

    dim3 gg(NPAD / 128, N_NODES / 256);   // (17, 8) = 136 CTAs, single wave

    prep_kernel<<<4193, 256>>>(E, x, st, Wg, Wu);

    // gate gconv (folded): X1T = (A X0)T ; Y2T = (A X1)T
    mma_gemm<<<gg, 256, SMEM_BYTES>>>(pAh, pT0, pT1);
    mma_gemm<<<gg, 256, SMEM_BYTES>>>(pAh, pT1, pT2);

    gate_kernel<<<(BATCH * N_NODES) / 16, 128>>>(x, st, bg);  // C0T in place

    // update gconv (folded): C1T = (A C0)T ; Y4T = (A C1)T
    mma_gemm<<<gg, 256, SMEM_BYTES>>>(pAh, pT0, pT1);
    mma_gemm<<<gg, 256, SMEM_BYTES>>>(pAh, pT1, pT2);

    update_kernel<<<(BATCH * N_NODES) / 16, 128>>>(st, bu, out);
}